// round 6
// baseline (speedup 1.0000x reference)
#include <cuda_runtime.h>
#include <cstdint>
#include <math.h>

#define T_TOK 1024
#define HDIM  1024
#define NEXP  16
#define TOPK  4
#define NPAIR (T_TOK*TOPK)

__device__ float g_tnorm[T_TOK*HDIM];
__device__ float g_act[NPAIR*HDIM];
__device__ float g_y[NPAIR*HDIM];
__device__ float g_wgt[NPAIR];
__device__ int   g_plist[NEXP*T_TOK];
__device__ int   g_cnt[NEXP];

// ---------------- helpers ----------------
__device__ __forceinline__ uint32_t smem_u32(const void* p) {
    uint32_t a;
    asm("{ .reg .u64 t; cvta.to.shared.u64 t, %1; cvt.u32.u64 %0, t; }" : "=r"(a) : "l"(p));
    return a;
}
__device__ __forceinline__ void cp16(uint32_t dst, const void* src, int srcbytes) {
    asm volatile("cp.async.cg.shared.global [%0], [%1], 16, %2;"
                 :: "r"(dst), "l"(src), "r"(srcbytes) : "memory");
}
__device__ __forceinline__ void cp_commit() {
    asm volatile("cp.async.commit_group;" ::: "memory");
}
template<int N> __device__ __forceinline__ void cp_wait() {
    asm volatile("cp.async.wait_group %0;" :: "n"(N) : "memory");
}
__device__ __forceinline__ void mma1688(float* d, const uint32_t* a, const uint32_t* b) {
    asm volatile("mma.sync.aligned.m16n8k8.row.col.f32.tf32.tf32.f32 "
                 "{%0,%1,%2,%3}, {%4,%5,%6,%7}, {%8,%9}, {%0,%1,%2,%3};"
                 : "+f"(d[0]), "+f"(d[1]), "+f"(d[2]), "+f"(d[3])
                 : "r"(a[0]), "r"(a[1]), "r"(a[2]), "r"(a[3]), "r"(b[0]), "r"(b[1]));
}

__global__ void k_zero() { if (threadIdx.x < NEXP) g_cnt[threadIdx.x] = 0; }

// ---------------- RMSNorm + router + top-4 + dispatch ----------------
__global__ void k_norm_router(const float* __restrict__ x, const float* __restrict__ nw,
                              const float* __restrict__ rw, const float* __restrict__ rb,
                              const float* __restrict__ mw, const int* __restrict__ lip)
{
    const int t = blockIdx.x, tid = threadIdx.x;
    const int wid = tid >> 5, lane = tid & 31;

    float4 xv = ((const float4*)(x + (size_t)t * HDIM))[tid];
    float ss = xv.x*xv.x + xv.y*xv.y + xv.z*xv.z + xv.w*xv.w;

    __shared__ float sw8[8];
    #pragma unroll
    for (int o = 16; o; o >>= 1) ss += __shfl_xor_sync(~0u, ss, o);
    if (lane == 0) sw8[wid] = ss;
    __syncthreads();
    __shared__ float s_scale;
    if (tid == 0) {
        float tot = 0.f;
        #pragma unroll
        for (int i = 0; i < 8; i++) tot += sw8[i];
        s_scale = rsqrtf(tot / (float)HDIM + 1e-5f);
    }
    __syncthreads();
    const float s = s_scale;

    float4 nv = ((const float4*)nw)[tid];
    float4 tv = make_float4(xv.x*s*nv.x, xv.y*s*nv.y, xv.z*s*nv.z, xv.w*s*nv.w);
    ((float4*)(g_tnorm + (size_t)t * HDIM))[tid] = tv;

    float p[NEXP];
    #pragma unroll
    for (int e = 0; e < NEXP; e++) {
        float4 wv = ((const float4*)(rw + (size_t)e * HDIM))[tid];
        p[e] = tv.x*wv.x + tv.y*wv.y + tv.z*wv.z + tv.w*wv.w;
    }
    __shared__ float sall[8][NEXP];
    #pragma unroll
    for (int e = 0; e < NEXP; e++) {
        float v = p[e];
        #pragma unroll
        for (int o = 16; o; o >>= 1) v += __shfl_xor_sync(~0u, v, o);
        if (lane == 0) sall[wid][e] = v;
    }
    __syncthreads();

    if (tid == 0) {
        float g[NEXP];
        #pragma unroll
        for (int e = 0; e < NEXP; e++) {
            float v = 0.f;
            #pragma unroll
            for (int w = 0; w < 8; w++) v += sall[w][e];
            g[e] = v + rb[e];
        }
        const int li = lip ? lip[0] : 0;
        float ma = 0.f;
        #pragma unroll
        for (int e = 0; e < NEXP; e++) ma = fmaxf(ma, fabsf(mw[li*NEXP + e]));
        if (ma > 0.f) {
            float m = -1e30f;
            for (int e = 0; e < NEXP; e++) m = fmaxf(m, g[e]);
            float se = 0.f;
            for (int e = 0; e < NEXP; e++) se += expf(g[e] - m);
            const float lse = m + logf(se);
            float gl[NEXP], mx = -1e30f, mn = 1e30f;
            for (int e = 0; e < NEXP; e++) {
                gl[e] = g[e] - lse;
                mx = fmaxf(mx, gl[e]); mn = fminf(mn, gl[e]);
            }
            for (int e = 0; e < NEXP; e++) {
                const float l = mw[li*NEXP + e];
                g[e] = (l > 0.f) ? mx + 0.01f : (l < 0.f) ? mn - 0.01f : gl[e];
            }
        }
        int idx[TOPK]; float val[TOPK]; unsigned used = 0;
        #pragma unroll
        for (int k = 0; k < TOPK; k++) {
            int b = 0; float bv = -1e38f;
            for (int e = 0; e < NEXP; e++)
                if (!((used >> e) & 1u) && g[e] > bv) { bv = g[e]; b = e; }
            used |= 1u << b; idx[k] = b; val[k] = bv;
        }
        const float m0 = val[0];
        float wsum = 0.f, wv2[TOPK];
        #pragma unroll
        for (int k = 0; k < TOPK; k++) { wv2[k] = expf(val[k] - m0); wsum += wv2[k]; }
        #pragma unroll
        for (int k = 0; k < TOPK; k++) {
            const int e = idx[k];
            const int pos = atomicAdd(&g_cnt[e], 1);
            g_plist[e * T_TOK + pos] = t * TOPK + k;
            g_wgt[t * TOPK + k] = wv2[k] / wsum;
        }
    }
}

// ---------------- tf32 mma.sync GEMM, 128x256 CTA tile, 64x64 warp tile -----
#define ASTR 20
#define BSTR 264
#define AFL  (128*ASTR)            // 2560 floats per A stage
#define BFL  (16*BSTR)             // 4224 floats per B stage
#define ABYT (AFL*4)
#define BBYT (BFL*4)
#define SMEM_MMA ((4*AFL + 4*BFL) * 4)   // 108544 bytes

template<int IS_G1>
__global__ __launch_bounds__(256, 1)
void k_mma(const float* __restrict__ W, const float* __restrict__ bias)
{
    const int e = blockIdx.z;
    const int n = g_cnt[e];
    const int row0 = blockIdx.y * 128;
    if (row0 >= n) return;

    extern __shared__ float dsm[];
    __shared__ float sbias[256];
    __shared__ int   spid[128];
    __shared__ float swgt[128];

    const int tid = threadIdx.x, lane = tid & 31, wid = tid >> 5;
    const int g = lane >> 2, tg = lane & 3;
    const int warp_m = wid >> 2, warp_n = wid & 3;
    // G1: CTA covers i-cols [c0, c0+128) => gate cols c0.., up cols 1024+c0..
    // G2: CTA covers h-cols [c0, c0+256)
    const int c0 = blockIdx.x * (IS_G1 ? 128 : 256);

    if (tid < 128) {
        const int r = row0 + tid;
        const int p = (r < n) ? g_plist[e * T_TOK + r] : -1;
        spid[tid] = p;
        if (!IS_G1) swgt[tid] = (p >= 0) ? g_wgt[p] : 0.f;
    }
    if (IS_G1)
        sbias[tid] = (tid < 128) ? bias[e*2048 + c0 + tid]
                                 : bias[e*2048 + 1024 + c0 + (tid - 128)];
    else
        sbias[tid] = bias[e*1024 + c0 + tid];
    __syncthreads();

    // ---- staging source setup ----
    const float* Aglob = IS_G1 ? g_tnorm : g_act;
    const int arow = tid >> 1;                 // 0..127
    const int akc  = (tid & 1) * 8;
    const int apid = spid[arow];
    const long aoff = (apid < 0) ? 0 : (IS_G1 ? (long)(apid >> 2) * HDIM : (long)apid * HDIM);
    const int avalid = (apid >= 0) ? 16 : 0;

    const int bk  = tid >> 4;                  // 0..15 (k row)
    const int bcl = (tid & 15) * 16;           // smem col group 0..240
    const long bstride = IS_G1 ? 2048 : 1024;
    const float* Wg = W + (size_t)e * (size_t)bstride * 1024;
    long bcol;
    if (IS_G1) bcol = (bcl < 128) ? (long)(c0 + bcl) : (long)(1024 + c0 + (bcl - 128));
    else       bcol = (long)(c0 + bcl);

    const uint32_t sA = smem_u32(dsm);
    const uint32_t sB = sA + 4 * ABYT;
    const uint32_t aDst = sA + (uint32_t)(arow * ASTR + akc) * 4;
    const uint32_t bDst = sB + (uint32_t)(bk * BSTR + bcl) * 4;

    float acc[4][8][4];
    #pragma unroll
    for (int i = 0; i < 4; i++)
        #pragma unroll
        for (int j = 0; j < 8; j++)
            #pragma unroll
            for (int q = 0; q < 4; q++) acc[i][j][q] = 0.f;

    int nbase[8];
    #pragma unroll
    for (int nt = 0; nt < 8; nt++)
        nbase[nt] = IS_G1 ? ((nt < 4) ? warp_n*32 + nt*8 : 128 + warp_n*32 + (nt-4)*8)
                          : warp_n*64 + nt*8;

    // ---- prologue: stages 0..2 ----
    #pragma unroll
    for (int s = 0; s < 3; s++) {
        const int k0 = s * 16;
        const float* asrc = Aglob + aoff + k0 + akc;
        cp16(aDst + s*ABYT,      asrc,     avalid);
        cp16(aDst + s*ABYT + 16, asrc + 4, avalid);
        const float* bsrc = Wg + (size_t)(k0 + bk) * bstride + bcol;
        #pragma unroll
        for (int j = 0; j < 4; j++)
            cp16(bDst + s*BBYT + j*16, bsrc + j*4, 16);
        cp_commit();
    }

    #pragma unroll 1
    for (int it = 0; it < 64; it++) {
        if (it <= 61) cp_wait<2>();
        else if (it == 62) cp_wait<1>();
        else cp_wait<0>();
        __syncthreads();

        if (it + 3 < 64) {
            const int slot = (it + 3) & 3;
            const int k0 = (it + 3) * 16;
            const float* asrc = Aglob + aoff + k0 + akc;
            cp16(aDst + slot*ABYT,      asrc,     avalid);
            cp16(aDst + slot*ABYT + 16, asrc + 4, avalid);
            const float* bsrc = Wg + (size_t)(k0 + bk) * bstride + bcol;
            #pragma unroll
            for (int j = 0; j < 4; j++)
                cp16(bDst + slot*BBYT + j*16, bsrc + j*4, 16);
            cp_commit();
        }

        const int buf = it & 3;
        const float* Ab = dsm + buf * AFL;
        const float* Bb = dsm + 4*AFL + buf * BFL;
        #pragma unroll
        for (int s = 0; s < 2; s++) {
            uint32_t af[4][4];
            #pragma unroll
            for (int mt = 0; mt < 4; mt++) {
                const int rb_ = warp_m*64 + mt*16 + g;
                const int cb = s*8 + tg;
                af[mt][0] = __float_as_uint(Ab[rb_       * ASTR + cb]);
                af[mt][1] = __float_as_uint(Ab[(rb_ + 8) * ASTR + cb]);
                af[mt][2] = __float_as_uint(Ab[rb_       * ASTR + cb + 4]);
                af[mt][3] = __float_as_uint(Ab[(rb_ + 8) * ASTR + cb + 4]);
            }
            uint32_t bf[8][2];
            #pragma unroll
            for (int nt = 0; nt < 8; nt++) {
                const int nn = nbase[nt] + g;
                bf[nt][0] = __float_as_uint(Bb[(s*8 + tg)     * BSTR + nn]);
                bf[nt][1] = __float_as_uint(Bb[(s*8 + tg + 4) * BSTR + nn]);
            }
            #pragma unroll
            for (int mt = 0; mt < 4; mt++)
                #pragma unroll
                for (int nt = 0; nt < 8; nt++)
                    mma1688(acc[mt][nt], af[mt], bf[nt]);
        }
    }

    // ---- epilogue ----
    #pragma unroll
    for (int mt = 0; mt < 4; mt++) {
        const int r = warp_m*64 + mt*16 + g;
        const int p0 = spid[r], p1 = spid[r + 8];
        if (IS_G1) {
            #pragma unroll
            for (int nt = 0; nt < 4; nt++) {
                const int il = warp_n*32 + nt*8 + 2*tg;     // 0..127 within CTA
                const float bg0 = sbias[il], bg1 = sbias[il+1];
                const float bu0 = sbias[128+il], bu1 = sbias[128+il+1];
                #pragma unroll
                for (int h = 0; h < 2; h++) {
                    const int p = h ? p1 : p0;
                    if (p < 0) continue;
                    const float gt0 = fminf(acc[mt][nt][2*h]   + bg0, 7.0f);
                    const float gt1 = fminf(acc[mt][nt][2*h+1] + bg1, 7.0f);
                    const float u0 = fminf(fmaxf(acc[mt][nt+4][2*h]   + bu0, -7.0f), 7.0f);
                    const float u1 = fminf(fmaxf(acc[mt][nt+4][2*h+1] + bu1, -7.0f), 7.0f);
                    float* dst = g_act + (size_t)p * 1024 + c0 + il;
                    dst[0] = (u0 + 1.0f) * gt0 / (1.0f + __expf(-1.702f * gt0));
                    dst[1] = (u1 + 1.0f) * gt1 / (1.0f + __expf(-1.702f * gt1));
                }
            }
        } else {
            const float w0 = swgt[r], w1 = swgt[r + 8];
            #pragma unroll
            for (int nt = 0; nt < 8; nt++) {
                const int cl = warp_n*64 + nt*8 + 2*tg;     // 0..255 within CTA
                const float b0 = sbias[cl], b1 = sbias[cl+1];
                if (p0 >= 0) {
                    float* dst = g_y + (size_t)p0 * 1024 + c0 + cl;
                    dst[0] = (acc[mt][nt][0] + b0) * w0;
                    dst[1] = (acc[mt][nt][1] + b1) * w0;
                }
                if (p1 >= 0) {
                    float* dst = g_y + (size_t)p1 * 1024 + c0 + cl;
                    dst[0] = (acc[mt][nt][2] + b0) * w1;
                    dst[1] = (acc[mt][nt][3] + b1) * w1;
                }
            }
        }
    }
}

// ---------------- residual + combine ----------------
__global__ void k_combine(const float* __restrict__ x, float* __restrict__ out)
{
    const int gid = blockIdx.x * blockDim.x + threadIdx.x;
    const int t = gid >> 8, c4 = gid & 255;
    float4 acc = ((const float4*)x)[gid];
    #pragma unroll
    for (int k = 0; k < TOPK; k++) {
        const float4 yv = ((const float4*)(g_y + (size_t)(t * TOPK + k) * HDIM))[c4];
        acc.x += yv.x; acc.y += yv.y; acc.z += yv.z; acc.w += yv.w;
    }
    ((float4*)out)[gid] = acc;
}

extern "C" void kernel_launch(void* const* d_in, const int* in_sizes, int n_in,
                              void* d_out, int out_size)
{
    const float* x   = (const float*)d_in[0];
    const float* nw  = (const float*)d_in[1];
    const float* rw  = (const float*)d_in[2];
    const float* rb  = (const float*)d_in[3];
    const float* w13 = (const float*)d_in[4];
    const float* b13 = (const float*)d_in[5];
    const float* w2  = (const float*)d_in[6];
    const float* b2  = (const float*)d_in[7];
    const float* mw  = (const float*)d_in[8];
    const int*   li  = (n_in >= 10) ? (const int*)d_in[9] : nullptr;
    float* out = (float*)d_out;

    cudaFuncSetAttribute((const void*)k_mma<1>,
                         cudaFuncAttributeMaxDynamicSharedMemorySize, SMEM_MMA);
    cudaFuncSetAttribute((const void*)k_mma<0>,
                         cudaFuncAttributeMaxDynamicSharedMemorySize, SMEM_MMA);

    k_zero<<<1, 32>>>();
    k_norm_router<<<T_TOK, 256>>>(x, nw, rw, rb, mw, li);
    k_mma<1><<<dim3(8, 8, NEXP), 256, SMEM_MMA>>>(w13, b13);
    k_mma<0><<<dim3(4, 8, NEXP), 256, SMEM_MMA>>>(w2, b2);
    k_combine<<<(T_TOK * HDIM / 4) / 256, 256>>>(x, out);
}

// round 7
// speedup vs baseline: 1.8610x; 1.8610x over previous
#include <cuda_runtime.h>
#include <cuda_fp16.h>
#include <cstdint>
#include <math.h>

#define T_TOK 1024
#define HDIM  1024
#define NEXP  16
#define TOPK  4
#define NPAIR (T_TOK*TOPK)

__device__ __half g_tnormh[T_TOK*HDIM];   // fp16 normalized activations (2 MB)
__device__ __half g_acth[NPAIR*HDIM];     // fp16 post-activation (8 MB)
__device__ float  g_y[NPAIR*HDIM];        // per-pair expert output (16 MB)
__device__ float  g_wgt[NPAIR];
__device__ int    g_plist[NEXP*T_TOK];
__device__ int    g_cnt[NEXP];

// ---------------- helpers ----------------
__device__ __forceinline__ uint32_t smem_u32(const void* p) {
    uint32_t a;
    asm("{ .reg .u64 t; cvta.to.shared.u64 t, %1; cvt.u32.u64 %0, t; }" : "=r"(a) : "l"(p));
    return a;
}
__device__ __forceinline__ void cp16(uint32_t dst, const void* src, int srcbytes) {
    asm volatile("cp.async.cg.shared.global [%0], [%1], 16, %2;"
                 :: "r"(dst), "l"(src), "r"(srcbytes) : "memory");
}
__device__ __forceinline__ void cp_commit() {
    asm volatile("cp.async.commit_group;" ::: "memory");
}
template<int N> __device__ __forceinline__ void cp_wait() {
    asm volatile("cp.async.wait_group %0;" :: "n"(N) : "memory");
}
// pack two f32 -> f16x2 (lo = first arg, hi = second arg)
__device__ __forceinline__ uint32_t packh2(float lo, float hi) {
    uint32_t r;
    asm("cvt.rn.f16x2.f32 %0, %1, %2;" : "=r"(r) : "f"(hi), "f"(lo));
    return r;
}
__device__ __forceinline__ void mma16816(float* d, const uint32_t* a, const uint32_t* b) {
    asm volatile("mma.sync.aligned.m16n8k16.row.col.f32.f16.f16.f32 "
                 "{%0,%1,%2,%3}, {%4,%5,%6,%7}, {%8,%9}, {%0,%1,%2,%3};"
                 : "+f"(d[0]), "+f"(d[1]), "+f"(d[2]), "+f"(d[3])
                 : "r"(a[0]), "r"(a[1]), "r"(a[2]), "r"(a[3]), "r"(b[0]), "r"(b[1]));
}

__global__ void k_zero() { if (threadIdx.x < NEXP) g_cnt[threadIdx.x] = 0; }

// ---------------- RMSNorm + router + top-4 + dispatch ----------------
__global__ void k_norm_router(const float* __restrict__ x, const float* __restrict__ nw,
                              const float* __restrict__ rw, const float* __restrict__ rb,
                              const float* __restrict__ mw, const int* __restrict__ lip)
{
    const int t = blockIdx.x, tid = threadIdx.x;
    const int wid = tid >> 5, lane = tid & 31;

    float4 xv = ((const float4*)(x + (size_t)t * HDIM))[tid];
    float ss = xv.x*xv.x + xv.y*xv.y + xv.z*xv.z + xv.w*xv.w;

    __shared__ float sw8[8];
    #pragma unroll
    for (int o = 16; o; o >>= 1) ss += __shfl_xor_sync(~0u, ss, o);
    if (lane == 0) sw8[wid] = ss;
    __syncthreads();
    __shared__ float s_scale;
    if (tid == 0) {
        float tot = 0.f;
        #pragma unroll
        for (int i = 0; i < 8; i++) tot += sw8[i];
        s_scale = rsqrtf(tot / (float)HDIM + 1e-5f);
    }
    __syncthreads();
    const float s = s_scale;

    float4 nv = ((const float4*)nw)[tid];
    float4 tv = make_float4(xv.x*s*nv.x, xv.y*s*nv.y, xv.z*s*nv.z, xv.w*s*nv.w);
    {
        __half2* th = (__half2*)(g_tnormh + (size_t)t * HDIM);
        th[tid*2]   = __floats2half2_rn(tv.x, tv.y);
        th[tid*2+1] = __floats2half2_rn(tv.z, tv.w);
    }

    float p[NEXP];
    #pragma unroll
    for (int e = 0; e < NEXP; e++) {
        float4 wv = ((const float4*)(rw + (size_t)e * HDIM))[tid];
        p[e] = tv.x*wv.x + tv.y*wv.y + tv.z*wv.z + tv.w*wv.w;
    }
    __shared__ float sall[8][NEXP];
    #pragma unroll
    for (int e = 0; e < NEXP; e++) {
        float v = p[e];
        #pragma unroll
        for (int o = 16; o; o >>= 1) v += __shfl_xor_sync(~0u, v, o);
        if (lane == 0) sall[wid][e] = v;
    }
    __syncthreads();

    if (tid == 0) {
        float g[NEXP];
        #pragma unroll
        for (int e = 0; e < NEXP; e++) {
            float v = 0.f;
            #pragma unroll
            for (int w = 0; w < 8; w++) v += sall[w][e];
            g[e] = v + rb[e];
        }
        const int li = lip ? lip[0] : 0;
        float ma = 0.f;
        #pragma unroll
        for (int e = 0; e < NEXP; e++) ma = fmaxf(ma, fabsf(mw[li*NEXP + e]));
        if (ma > 0.f) {
            float m = -1e30f;
            for (int e = 0; e < NEXP; e++) m = fmaxf(m, g[e]);
            float se = 0.f;
            for (int e = 0; e < NEXP; e++) se += expf(g[e] - m);
            const float lse = m + logf(se);
            float gl[NEXP], mx = -1e30f, mn = 1e30f;
            for (int e = 0; e < NEXP; e++) {
                gl[e] = g[e] - lse;
                mx = fmaxf(mx, gl[e]); mn = fminf(mn, gl[e]);
            }
            for (int e = 0; e < NEXP; e++) {
                const float l = mw[li*NEXP + e];
                g[e] = (l > 0.f) ? mx + 0.01f : (l < 0.f) ? mn - 0.01f : gl[e];
            }
        }
        int idx[TOPK]; float val[TOPK]; unsigned used = 0;
        #pragma unroll
        for (int k = 0; k < TOPK; k++) {
            int b = 0; float bv = -1e38f;
            for (int e = 0; e < NEXP; e++)
                if (!((used >> e) & 1u) && g[e] > bv) { bv = g[e]; b = e; }
            used |= 1u << b; idx[k] = b; val[k] = bv;
        }
        const float m0 = val[0];
        float wsum = 0.f, wv2[TOPK];
        #pragma unroll
        for (int k = 0; k < TOPK; k++) { wv2[k] = expf(val[k] - m0); wsum += wv2[k]; }
        #pragma unroll
        for (int k = 0; k < TOPK; k++) {
            const int e = idx[k];
            const int pos = atomicAdd(&g_cnt[e], 1);
            g_plist[e * T_TOK + pos] = t * TOPK + k;
            g_wgt[t * TOPK + k] = wv2[k] / wsum;
        }
    }
}

// ---------------- fp16 mma.sync GEMM, 128x128 CTA, 64x32 warp, 4-stage -----
#define ASTRH 24                    // halves per A row (16 data + 8 pad)
#define BSTR  132                   // floats per B row (128 data + 4 pad)
#define ABYT  (128*ASTRH*2)         // 6144 B per A stage
#define BBYT  (16*BSTR*4)           // 8448 B per B stage
#define SMEM_MMA (4*(ABYT + BBYT))  // 58368 B

template<int IS_G1>
__global__ __launch_bounds__(256, 2)
void k_mma(const float* __restrict__ W, const float* __restrict__ bias)
{
    const int e = blockIdx.z;
    const int n = g_cnt[e];
    const int row0 = blockIdx.y * 128;
    if (row0 >= n) return;

    extern __shared__ char dsm[];
    __shared__ float sbias[128];
    __shared__ int   spid[128];
    __shared__ float swgt[128];

    const int tid = threadIdx.x, lane = tid & 31, wid = tid >> 5;
    const int g = lane >> 2, tg = lane & 3;
    const int warp_m = wid >> 2, warp_n = wid & 3;
    const int c0 = blockIdx.x * (IS_G1 ? 64 : 128);

    if (tid < 128) {
        const int r = row0 + tid;
        const int p = (r < n) ? g_plist[e * T_TOK + r] : -1;
        spid[tid] = p;
        if (!IS_G1) swgt[tid] = (p >= 0) ? g_wgt[p] : 0.f;
        if (IS_G1)
            sbias[tid] = (tid < 64) ? bias[e*2048 + c0 + tid]
                                    : bias[e*2048 + 1024 + c0 + (tid - 64)];
        else
            sbias[tid] = bias[e*1024 + c0 + tid];
    }
    __syncthreads();

    // ---- staging source setup ----
    const __half* Aglob = IS_G1 ? g_tnormh : g_acth;
    const int arow = tid >> 1;                 // 0..127
    const int akc  = (tid & 1) * 8;            // half-element offset 0 or 8
    const int apid = spid[arow];
    const long aoff = (apid < 0) ? 0 : (IS_G1 ? (long)(apid >> 2) * HDIM : (long)apid * HDIM);
    const int avalid = (apid >= 0) ? 16 : 0;

    const int bk  = tid >> 4;                  // 0..15 (k row)
    const int bcl = (tid & 15) * 8;            // smem col 0..120
    const long bstride = IS_G1 ? 2048 : 1024;
    const float* Wg = W + (size_t)e * (size_t)bstride * 1024;
    long bcol;
    if (IS_G1) bcol = (bcl < 64) ? (long)(c0 + bcl) : (long)(1024 + c0 + (bcl - 64));
    else       bcol = (long)(c0 + bcl);

    const uint32_t sA = smem_u32(dsm);
    const uint32_t sB = sA + 4 * ABYT;
    const uint32_t aDst = sA + (uint32_t)(arow * ASTRH + akc) * 2;
    const uint32_t bDst = sB + (uint32_t)(bk * BSTR + bcl) * 4;

    float acc[4][4][4];
    #pragma unroll
    for (int i = 0; i < 4; i++)
        #pragma unroll
        for (int j = 0; j < 4; j++)
            #pragma unroll
            for (int q = 0; q < 4; q++) acc[i][j][q] = 0.f;

    int nbase[4];
    #pragma unroll
    for (int nt = 0; nt < 4; nt++)
        nbase[nt] = IS_G1 ? ((nt < 2) ? warp_n*16 + nt*8 : 64 + warp_n*16 + (nt-2)*8)
                          : warp_n*32 + nt*8;

    // ---- prologue: stages 0..2 ----
    #pragma unroll
    for (int s = 0; s < 3; s++) {
        const int k0 = s * 16;
        cp16(aDst + s*ABYT, Aglob + aoff + k0 + akc, avalid);
        const float* bsrc = Wg + (size_t)(k0 + bk) * bstride + bcol;
        cp16(bDst + s*BBYT,      bsrc,     16);
        cp16(bDst + s*BBYT + 16, bsrc + 4, 16);
        cp_commit();
    }

    #pragma unroll 1
    for (int it = 0; it < 64; it++) {
        if (it <= 61) cp_wait<2>();
        else if (it == 62) cp_wait<1>();
        else cp_wait<0>();
        __syncthreads();

        if (it + 3 < 64) {
            const int slot = (it + 3) & 3;
            const int k0 = (it + 3) * 16;
            cp16(aDst + slot*ABYT, Aglob + aoff + k0 + akc, avalid);
            const float* bsrc = Wg + (size_t)(k0 + bk) * bstride + bcol;
            cp16(bDst + slot*BBYT,      bsrc,     16);
            cp16(bDst + slot*BBYT + 16, bsrc + 4, 16);
            cp_commit();
        }

        const int buf = it & 3;
        const __half* Ab = (const __half*)(dsm + buf * ABYT);
        const float*  Bb = (const float*)(dsm + 4*ABYT + buf * BBYT);

        uint32_t af[4][4];
        #pragma unroll
        for (int mt = 0; mt < 4; mt++) {
            const int r_ = warp_m*64 + mt*16 + g;
            af[mt][0] = *(const uint32_t*)(Ab + r_       * ASTRH + 2*tg);
            af[mt][1] = *(const uint32_t*)(Ab + (r_ + 8) * ASTRH + 2*tg);
            af[mt][2] = *(const uint32_t*)(Ab + r_       * ASTRH + 2*tg + 8);
            af[mt][3] = *(const uint32_t*)(Ab + (r_ + 8) * ASTRH + 2*tg + 8);
        }
        uint32_t bf[4][2];
        #pragma unroll
        for (int nt = 0; nt < 4; nt++) {
            const int nn = nbase[nt] + g;
            bf[nt][0] = packh2(Bb[(2*tg)     * BSTR + nn], Bb[(2*tg + 1) * BSTR + nn]);
            bf[nt][1] = packh2(Bb[(2*tg + 8) * BSTR + nn], Bb[(2*tg + 9) * BSTR + nn]);
        }
        #pragma unroll
        for (int mt = 0; mt < 4; mt++)
            #pragma unroll
            for (int nt = 0; nt < 4; nt++)
                mma16816(acc[mt][nt], af[mt], bf[nt]);
    }

    // ---- epilogue ----
    #pragma unroll
    for (int mt = 0; mt < 4; mt++) {
        const int r = warp_m*64 + mt*16 + g;
        const int p0 = spid[r], p1 = spid[r + 8];
        if (IS_G1) {
            #pragma unroll
            for (int nt = 0; nt < 2; nt++) {
                const int il = warp_n*16 + nt*8 + 2*tg;
                const float bg0 = sbias[il], bg1 = sbias[il+1];
                const float bu0 = sbias[64+il], bu1 = sbias[64+il+1];
                #pragma unroll
                for (int h = 0; h < 2; h++) {
                    const int p = h ? p1 : p0;
                    if (p < 0) continue;
                    const float gt0 = fminf(acc[mt][nt][2*h]   + bg0, 7.0f);
                    const float gt1 = fminf(acc[mt][nt][2*h+1] + bg1, 7.0f);
                    const float u0 = fminf(fmaxf(acc[mt][nt+2][2*h]   + bu0, -7.0f), 7.0f);
                    const float u1 = fminf(fmaxf(acc[mt][nt+2][2*h+1] + bu1, -7.0f), 7.0f);
                    const float v0 = (u0 + 1.0f) * gt0 / (1.0f + __expf(-1.702f * gt0));
                    const float v1 = (u1 + 1.0f) * gt1 / (1.0f + __expf(-1.702f * gt1));
                    *(__half2*)(g_acth + (size_t)p * 1024 + c0 + il) =
                        __floats2half2_rn(v0, v1);
                }
            }
        } else {
            const float w0 = swgt[r], w1 = swgt[r + 8];
            #pragma unroll
            for (int nt = 0; nt < 4; nt++) {
                const int cl = warp_n*32 + nt*8 + 2*tg;
                const float b0 = sbias[cl], b1 = sbias[cl+1];
                if (p0 >= 0) {
                    float* dst = g_y + (size_t)p0 * 1024 + c0 + cl;
                    dst[0] = (acc[mt][nt][0] + b0) * w0;
                    dst[1] = (acc[mt][nt][1] + b1) * w0;
                }
                if (p1 >= 0) {
                    float* dst = g_y + (size_t)p1 * 1024 + c0 + cl;
                    dst[0] = (acc[mt][nt][2] + b0) * w1;
                    dst[1] = (acc[mt][nt][3] + b1) * w1;
                }
            }
        }
    }
}

// ---------------- residual + combine ----------------
__global__ void k_combine(const float* __restrict__ x, float* __restrict__ out)
{
    const int gid = blockIdx.x * blockDim.x + threadIdx.x;
    const int t = gid >> 8, c4 = gid & 255;
    float4 acc = ((const float4*)x)[gid];
    #pragma unroll
    for (int k = 0; k < TOPK; k++) {
        const float4 yv = ((const float4*)(g_y + (size_t)(t * TOPK + k) * HDIM))[c4];
        acc.x += yv.x; acc.y += yv.y; acc.z += yv.z; acc.w += yv.w;
    }
    ((float4*)out)[gid] = acc;
}

extern "C" void kernel_launch(void* const* d_in, const int* in_sizes, int n_in,
                              void* d_out, int out_size)
{
    const float* x   = (const float*)d_in[0];
    const float* nw  = (const float*)d_in[1];
    const float* rw  = (const float*)d_in[2];
    const float* rb  = (const float*)d_in[3];
    const float* w13 = (const float*)d_in[4];
    const float* b13 = (const float*)d_in[5];
    const float* w2  = (const float*)d_in[6];
    const float* b2  = (const float*)d_in[7];
    const float* mw  = (const float*)d_in[8];
    const int*   li  = (n_in >= 10) ? (const int*)d_in[9] : nullptr;
    float* out = (float*)d_out;

    cudaFuncSetAttribute((const void*)k_mma<1>,
                         cudaFuncAttributeMaxDynamicSharedMemorySize, SMEM_MMA);
    cudaFuncSetAttribute((const void*)k_mma<0>,
                         cudaFuncAttributeMaxDynamicSharedMemorySize, SMEM_MMA);

    k_zero<<<1, 32>>>();
    k_norm_router<<<T_TOK, 256>>>(x, nw, rw, rb, mw, li);
    k_mma<1><<<dim3(16, 8, NEXP), 256, SMEM_MMA>>>(w13, b13);
    k_mma<0><<<dim3(8, 8, NEXP), 256, SMEM_MMA>>>(w2, b2);
    k_combine<<<(T_TOK * HDIM / 4) / 256, 256>>>(x, out);
}